// round 2
// baseline (speedup 1.0000x reference)
#include <cuda_runtime.h>
#include <cuda_bf16.h>

// LengthRegulator: out[b, t, :] = phoneme[b, tok(b,t), :]
// tok(b,t) = searchsorted_right(inclusive_cumsum(durations[b,:]), t), clip N-1.
// Shapes (fixed): B=16, N=256, D=512, T=2048. float32.

#define LR_B 16
#define LR_N 256
#define LR_D 512
#define LR_T 2048
#define FRAMES_PER_BLOCK 32
#define THREADS 256
#define VEC_PER_FRAME (LR_D / 4)   // 128 float4 per frame

__global__ __launch_bounds__(THREADS)
void length_regulator_kernel(const float4* __restrict__ phoneme4,
                             const int* __restrict__ durations,
                             float4* __restrict__ out4)
{
    const int b = blockIdx.y;
    const int frame_base = blockIdx.x * FRAMES_PER_BLOCK;
    const int tid = threadIdx.x;

    __shared__ int s_ends[LR_N];     // inclusive cumsum of durations[b,:]
    __shared__ int s_tok[FRAMES_PER_BLOCK];

    // 1) load durations row and inclusive scan (Hillis-Steele, blockDim==N==256)
    s_ends[tid] = durations[b * LR_N + tid];
    __syncthreads();
    #pragma unroll
    for (int off = 1; off < LR_N; off <<= 1) {
        int v = (tid >= off) ? s_ends[tid - off] : 0;
        __syncthreads();
        s_ends[tid] += v;
        __syncthreads();
    }

    // 2) lower-bound search: first token n with ends[n] > t.
    //    Range width 256 needs 9 bisection steps to reach width 0.
    if (tid < FRAMES_PER_BLOCK) {
        const int t = frame_base + tid;
        int lo = 0, hi = LR_N;
        #pragma unroll
        for (int it = 0; it < 9; ++it) {
            if (lo < hi) {
                int mid = (lo + hi) >> 1;
                if (s_ends[mid] > t) hi = mid; else lo = mid + 1;
            }
        }
        s_tok[tid] = (lo < LR_N) ? lo : (LR_N - 1);
    }
    __syncthreads();

    // 3) cooperative vectorized copy: 32 frames * 128 float4 = 4096 float4
    const float4* __restrict__ ph_b  = phoneme4 + (size_t)b * LR_N * VEC_PER_FRAME;
    float4* __restrict__       out_b = out4 + ((size_t)b * LR_T + frame_base) * VEC_PER_FRAME;

    #pragma unroll
    for (int i = tid; i < FRAMES_PER_BLOCK * VEC_PER_FRAME; i += THREADS) {
        const int f   = i >> 7;          // i / 128
        const int off = i & (VEC_PER_FRAME - 1);
        out_b[i] = ph_b[s_tok[f] * VEC_PER_FRAME + off];
    }
}

extern "C" void kernel_launch(void* const* d_in, const int* in_sizes, int n_in,
                              void* d_out, int out_size)
{
    const float4* phoneme4  = (const float4*)d_in[0];   // (B, N, D) f32
    const int*    durations = (const int*)d_in[1];      // (B, N) i32
    float4*       out4      = (float4*)d_out;           // (B, T, D) f32

    dim3 grid(LR_T / FRAMES_PER_BLOCK, LR_B);  // (64, 16)
    length_regulator_kernel<<<grid, THREADS>>>(phoneme4, durations, out4);
}